// round 9
// baseline (speedup 1.0000x reference)
#include <cuda_runtime.h>
#include <math.h>

#define NN   8192
#define EE   262144
#define CIN  64
#define DD   192      // IN_C*K = OUT_C*K
#define GG   64
#define NCLS 10
#define D3   576      // 3*DD
#define L1O  384
#define L2O  192
#define MAXDEG 128
#define BNEPS 1e-5f
#define NBF  (EE / 256)   // 1024 main fill blocks

// ---------------- scratch (no allocations allowed) ----------------
__device__ int      g_is64_batch;
__device__ int      g_cnt[NN];         // reset by spmm pass2 (after last read)
__device__ float    g_dinv[NN];
__device__ int      g_slot[NN * MAXDEG];
__device__ float    g_h1[NN * CIN];
__device__ float    g_h2[NN * CIN];
__device__ float    g_csum[DD], g_csq[DD];       // reset by fill zero-blocks
__device__ float    g_psum[GG * DD];             // raw per-(graph,col) sums
__device__ unsigned g_pmax[GG * DD];             // enc(max h), identity = 0
__device__ unsigned g_pmneg[GG * DD];            // enc(max -h), identity = 0
__device__ float    g_invsigma;

__device__ __forceinline__ int rd_idx(const void* p, int i, int is64) {
    if (is64) return (int)((const long long*)p)[i];
    return ((const int*)p)[i];
}

// monotone float<->uint map: unsigned compare preserves float order
__device__ __forceinline__ unsigned encf(float f) {
    unsigned u = __float_as_uint(f);
    return u ^ ((u >> 31) ? 0xFFFFFFFFu : 0x80000000u);
}
__device__ __forceinline__ float decf(unsigned u) {
    unsigned b = (u & 0x80000000u) ? (u ^ 0x80000000u) : ~u;
    return __uint_as_float(b);
}

// ---------------- fill: slot scatter + sigma + batch-detect + zero-resets --
__global__ void k_fill(const void* ei, const void* bt,
                       const float* __restrict__ W, const float* __restrict__ u) {
    int t = threadIdx.x;
    if (blockIdx.x == NBF) {
        // batch dtype detect (tail words: graph 63, nonzero iff int32)
        if (t == 0) {
            const int* wb = (const int*)bt;
            int bb = 0;
            #pragma unroll
            for (int k = NN - 64; k < NN; k++)
                if (k & 1) bb |= wb[k];
            g_is64_batch = (bb == 0) ? 1 : 0;
        }
        // sigma = ||W^T u||^2 / (||W^T u|| + 1e-12);  invsigma = 1/sigma
        __shared__ float red[256];
        __shared__ float su[DD];
        if (t < DD) su[t] = u[t];
        __syncthreads();
        float w = 0.f;
        if (t < DD) {
            #pragma unroll 8
            for (int i = 0; i < DD; i++) w += W[i * DD + t] * su[i];
        }
        red[t] = (t < DD) ? w * w : 0.f;
        __syncthreads();
        for (int off = 128; off > 0; off >>= 1) {
            if (t < off) red[t] += red[t + off];
            __syncthreads();
        }
        if (t == 0) {
            float n2 = red[0];
            g_invsigma = (sqrtf(n2) + 1e-12f) / n2;
        }
        return;
    }
    if (blockIdx.x > NBF) {
        // zero-reset accumulators for this run (before matmul uses them)
        int zi = (blockIdx.x - NBF - 1) * 256 + t;   // 0..1023 over 4 blocks
        for (int i = zi; i < GG * DD; i += 1024) {
            g_psum[i] = 0.f; g_pmax[i] = 0u; g_pmneg[i] = 0u;
        }
        if (zi < DD) { g_csum[zi] = 0.f; g_csq[zi] = 0.f; }
        return;
    }
    // main: edge dtype detect per block, then slot fill
    __shared__ int sflag;
    if (t == 0) {
        const int* w = (const int*)ei;
        int a = 0;
        #pragma unroll
        for (int k = 0; k < 32; k++) a |= w[2 * k + 1];
        sflag = (a == 0) ? 1 : 0;
    }
    __syncthreads();
    int is64 = sflag;
    int e = blockIdx.x * 256 + t;
    int r = rd_idx(ei, e, is64);
    int c = rd_idx(ei, EE + e, is64);
    int pos = atomicAdd(&g_cnt[r], 1);
    if (pos < MAXDEG) g_slot[r * MAXDEG + pos] = c;
}

// ---- gather SpMM: out[r] = in[r] - dinv[r]*sum_c dinv[c]*in[c]
// PASS1: dinv from cnt (rsqrt per edge), caches g_dinv. PASS2: reads g_dinv,
// then resets g_cnt for the next replay.
template <int PASS1>
__global__ void k_spmm(const float* __restrict__ in, float* __restrict__ out) {
    int node = blockIdx.x * 8 + (threadIdx.x >> 5);
    int lane = threadIdx.x & 31;
    const float2* in2 = (const float2*)in;
    int cr = g_cnt[node];
    int cnt = min(cr, MAXDEG);
    float dvr;
    if (PASS1) {
        dvr = (cr > 0) ? rsqrtf((float)cr) : 0.f;
        if (lane == 0) g_dinv[node] = dvr;
    } else {
        dvr = g_dinv[node];
        if (lane == 0) g_cnt[node] = 0;   // reset after last read
    }
    float2 sum = make_float2(0.f, 0.f);
    const int* sl = g_slot + node * MAXDEG;
    const int4* sl4 = (const int4*)sl;
    int j = 0;
    for (; j + 8 <= cnt; j += 8) {
        int4 a = sl4[j >> 2], b2 = sl4[(j >> 2) + 1];
        int c[8] = {a.x, a.y, a.z, a.w, b2.x, b2.y, b2.z, b2.w};
        float dv[8];
        #pragma unroll
        for (int k = 0; k < 8; k++) {
            if (PASS1) {
                int cc = g_cnt[c[k]];
                dv[k] = (cc > 0) ? rsqrtf((float)cc) : 0.f;
            } else {
                dv[k] = g_dinv[c[k]];
            }
        }
        #pragma unroll
        for (int k = 0; k < 8; k++) {
            float2 v = in2[c[k] * 32 + lane];
            sum.x += dv[k] * v.x;
            sum.y += dv[k] * v.y;
        }
    }
    for (; j < cnt; j++) {
        int c = sl[j];
        float dv;
        if (PASS1) {
            int cc = g_cnt[c];
            dv = (cc > 0) ? rsqrtf((float)cc) : 0.f;
        } else {
            dv = g_dinv[c];
        }
        float2 v = in2[c * 32 + lane];
        sum.x += dv * v.x;
        sum.y += dv * v.y;
    }
    float2 xv = in2[node * 32 + lane];
    ((float2*)out)[node * 32 + lane] =
        make_float2(xv.x - dvr * sum.x, xv.y - dvr * sum.y);
}

// ---------------- masked spectral linear + fused BN1 stats + raw pooling ---
// 128 rows x 64 cols per block, 256 threads, 8x4 micro-tile, BK=16.
// Block-lower-triangular mask => out-col tile obi needs only K < 64*(obi+1).
// Epilogue: per-column global sum/sumsq atomics + per-(graph,col) raw
// sum/max/min atomics. hlin is never materialized.
__global__ void k_matmul(const float* __restrict__ x, const float* __restrict__ W,
                         const float* __restrict__ b, const void* bt) {
    __shared__ float As[16][132];
    __shared__ float Bs[16][68];
    __shared__ int sbatch[128];
    int obi = 2 - blockIdx.x;     // longest K first
    int ob = obi * 64;
    int kmax = 64 * (obi + 1);
    int rb = blockIdx.y * 128;
    int t = threadIdx.x;
    int tx = t & 15, ty = t >> 4;
    float acc[8][4];
    #pragma unroll
    for (int i = 0; i < 8; i++)
        #pragma unroll
        for (int j = 0; j < 4; j++) acc[i][j] = 0.f;
    float invs = g_invsigma;

    int lidx = t * 4;
    int lm = lidx >> 4;       // 0..63
    int lk = lidx & 15;       // 0,4,8,12

    for (int kb = 0; kb < kmax; kb += 16) {
        int kg = kb + lk;
        int seg = kg >> 6;
        const float* src = (seg == 0) ? x : ((seg == 1) ? g_h1 : g_h2);
        #pragma unroll
        for (int rep = 0; rep < 2; rep++) {
            int row = rb + lm + rep * 64;
            float4 v = *(const float4*)(src + row * CIN + (kg & 63));
            As[lk][lm + rep * 64]     = v.x;
            As[lk + 1][lm + rep * 64] = v.y;
            As[lk + 2][lm + rep * 64] = v.z;
            As[lk + 3][lm + rep * 64] = v.w;
        }
        {
            float4 v = *(const float4*)(W + (ob + lm) * DD + kg);
            Bs[lk][lm]     = v.x * invs;
            Bs[lk + 1][lm] = v.y * invs;
            Bs[lk + 2][lm] = v.z * invs;
            Bs[lk + 3][lm] = v.w * invs;
        }
        __syncthreads();
        #pragma unroll
        for (int kk = 0; kk < 16; kk++) {
            float av[8], bv[4];
            #pragma unroll
            for (int i = 0; i < 8; i++) av[i] = As[kk][ty * 8 + i];
            #pragma unroll
            for (int j = 0; j < 4; j++) bv[j] = Bs[kk][tx * 4 + j];
            #pragma unroll
            for (int i = 0; i < 8; i++)
                #pragma unroll
                for (int j = 0; j < 4; j++) acc[i][j] += av[i] * bv[j];
        }
        __syncthreads();
    }
    float bj[4];
    #pragma unroll
    for (int j = 0; j < 4; j++) bj[j] = b[ob + tx * 4 + j];

    // --- BN1 global stats over this tile's 128 rows ---
    float sj[4], qj[4];
    #pragma unroll
    for (int j = 0; j < 4; j++) {
        float s = 0.f, q = 0.f;
        #pragma unroll
        for (int i = 0; i < 8; i++) {
            float v = acc[i][j] + bj[j];
            s += v; q += v * v;
        }
        sj[j] = s; qj[j] = q;
    }
    #pragma unroll
    for (int j = 0; j < 4; j++) {
        As[ty][tx * 4 + j] = sj[j];
        Bs[ty][tx * 4 + j] = qj[j];
    }
    if (t < 128) sbatch[t] = rd_idx(bt, rb + t, g_is64_batch);
    __syncthreads();
    if (t < 64) {
        float s = 0.f, q = 0.f;
        #pragma unroll
        for (int k = 0; k < 16; k++) { s += As[k][t]; q += Bs[k][t]; }
        atomicAdd(&g_csum[ob + t], s);
        atomicAdd(&g_csq[ob + t], q);
    }
    __syncthreads();

    // --- raw segment pooling (sum / max / min) ---
    int gfirst = sbatch[0], glast = sbatch[127];
    for (int seg = gfirst; ; seg++) {
        float s[4], mx[4], mn[4];
        #pragma unroll
        for (int j = 0; j < 4; j++) { s[j] = 0.f; mx[j] = -INFINITY; mn[j] = INFINITY; }
        #pragma unroll
        for (int i = 0; i < 8; i++) {
            if (sbatch[ty * 8 + i] == seg) {
                #pragma unroll
                for (int j = 0; j < 4; j++) {
                    float v = acc[i][j] + bj[j];
                    s[j] += v;
                    mx[j] = fmaxf(mx[j], v);
                    mn[j] = fminf(mn[j], v);
                }
            }
        }
        #pragma unroll
        for (int j = 0; j < 4; j++) {
            As[ty][tx * 4 + j] = s[j];
            Bs[ty][tx * 4 + j] = mx[j];
        }
        __syncthreads();
        if (t < 64) {
            float ss = 0.f, mm = -INFINITY;
            #pragma unroll
            for (int k = 0; k < 16; k++) { ss += As[k][t]; mm = fmaxf(mm, Bs[k][t]); }
            atomicAdd(&g_psum[seg * DD + ob + t], ss);
            atomicMax(&g_pmax[seg * DD + ob + t], encf(mm));
        }
        __syncthreads();
        #pragma unroll
        for (int j = 0; j < 4; j++) As[ty][tx * 4 + j] = mn[j];
        __syncthreads();
        if (t < 64) {
            float mm = INFINITY;
            #pragma unroll
            for (int k = 0; k < 16; k++) mm = fminf(mm, As[k][t]);
            atomicMax(&g_pmneg[seg * DD + ob + t], encf(-mm));
        }
        if (seg == glast) break;
        __syncthreads();
    }
}

// ---------------- hg on the fly: BN1 affine of pooled raw stats ----------
__device__ __forceinline__ float hgval(int g, int c, const float* sa,
                                       const float* sb, const int* scnt) {
    int kind = c / DD;          // 0 avg, 1 sum, 2 max
    int cc = c - kind * DD;
    float a = sa[cc], bb = sb[cc];
    int cnt = scnt[g];
    if (kind == 2) {
        if (cnt == 0) return -INFINITY;
        float M = decf(g_pmax[g * DD + cc]);
        float m = -decf(g_pmneg[g * DD + cc]);
        return (a >= 0.f) ? a * M + bb : a * m + bb;
    }
    float sv = a * g_psum[g * DD + cc] + (float)cnt * bb;
    return (kind == 0) ? sv / fmaxf((float)cnt, 1.f) : sv;
}

// ---------------- fused BN1-finalize + BN2 + funnel MLP + log_softmax -----
__global__ void k_tail(const void* bt,
                       const float* __restrict__ g1, const float* __restrict__ be1,
                       const float* __restrict__ g2g, const float* __restrict__ g2b,
                       const float* __restrict__ w1, const float* __restrict__ b1,
                       const float* __restrict__ w2, const float* __restrict__ b2,
                       const float* __restrict__ w3, const float* __restrict__ b3,
                       float* __restrict__ out) {
    __shared__ float sa[DD], sb[DD];
    __shared__ int sstart[GG + 1];
    __shared__ int scnt[GG];
    __shared__ float smu[D3], srs[D3];
    __shared__ float xr[2][D3];
    __shared__ float x1[2][L1O];
    __shared__ float x2[2][L2O];
    int t = threadIdx.x;              // 384
    int g0 = blockIdx.x * 2;
    int w = t >> 5, lane = t & 31;

    if (t <= GG) {
        int is64 = g_is64_batch;
        int lo = 0, hi = NN;
        while (lo < hi) {
            int mid = (lo + hi) >> 1;
            if (rd_idx(bt, mid, is64) < t) lo = mid + 1; else hi = mid;
        }
        sstart[t] = lo;
    }
    if (t < DD) {
        float mu = g_csum[t] * (1.f / NN);
        float var = g_csq[t] * (1.f / NN) - mu * mu;
        float a = rsqrtf(var + BNEPS) * g1[t];
        sa[t] = a;
        sb[t] = be1[t] - mu * a;
    }
    __syncthreads();
    if (t < GG) scnt[t] = sstart[t + 1] - sstart[t];
    __syncthreads();

    // BN2 stats over graphs (hg computed on the fly)
    for (int c = t; c < D3; c += L1O) {
        float s = 0.f, q = 0.f;
        #pragma unroll 4
        for (int g = 0; g < GG; g++) {
            float v = hgval(g, c, sa, sb, scnt);
            s += v; q += v * v;
        }
        float m = s * (1.f / GG);
        float var = q * (1.f / GG) - m * m;
        smu[c] = m;
        srs[c] = rsqrtf(var + BNEPS);
    }
    __syncthreads();
    for (int c = t; c < D3; c += L1O) {
        float ga = g2g[c], be = g2b[c], m = smu[c], r = srs[c];
        xr[0][c] = ga * (hgval(g0, c, sa, sb, scnt) - m) * r + be;
        xr[1][c] = ga * (hgval(g0 + 1, c, sa, sb, scnt) - m) * r + be;
    }
    __syncthreads();
    {
        float a0 = b1[t], a1 = a0;
        const float4* wr = (const float4*)(w1 + t * D3);
        #pragma unroll 4
        for (int k = 0; k < D3 / 4; k++) {
            float4 wv = wr[k];
            a0 += xr[0][4 * k] * wv.x + xr[0][4 * k + 1] * wv.y
                + xr[0][4 * k + 2] * wv.z + xr[0][4 * k + 3] * wv.w;
            a1 += xr[1][4 * k] * wv.x + xr[1][4 * k + 1] * wv.y
                + xr[1][4 * k + 2] * wv.z + xr[1][4 * k + 3] * wv.w;
        }
        x1[0][t] = fmaxf(a0, 0.f);
        x1[1][t] = fmaxf(a1, 0.f);
    }
    __syncthreads();
    if (t < L2O) {
        float a0 = b2[t], a1 = a0;
        const float4* wr = (const float4*)(w2 + t * L1O);
        #pragma unroll 4
        for (int k = 0; k < L1O / 4; k++) {
            float4 wv = wr[k];
            a0 += x1[0][4 * k] * wv.x + x1[0][4 * k + 1] * wv.y
                + x1[0][4 * k + 2] * wv.z + x1[0][4 * k + 3] * wv.w;
            a1 += x1[1][4 * k] * wv.x + x1[1][4 * k + 1] * wv.y
                + x1[1][4 * k + 2] * wv.z + x1[1][4 * k + 3] * wv.w;
        }
        x2[0][t] = fmaxf(a0, 0.f);
        x2[1][t] = fmaxf(a1, 0.f);
    }
    __syncthreads();
    if (w < 2) {
        float z = -INFINITY;
        if (lane < NCLS) {
            z = b3[lane];
            const float4* wr = (const float4*)(w3 + lane * L2O);
            #pragma unroll 4
            for (int k = 0; k < L2O / 4; k++) {
                float4 wv = wr[k];
                z += x2[w][4 * k] * wv.x + x2[w][4 * k + 1] * wv.y
                   + x2[w][4 * k + 2] * wv.z + x2[w][4 * k + 3] * wv.w;
            }
        }
        float m = z;
        #pragma unroll
        for (int off = 16; off > 0; off >>= 1)
            m = fmaxf(m, __shfl_xor_sync(0xffffffff, m, off));
        float ex = (lane < NCLS) ? __expf(z - m) : 0.f;
        float ssum = ex;
        #pragma unroll
        for (int off = 16; off > 0; off >>= 1)
            ssum += __shfl_xor_sync(0xffffffff, ssum, off);
        float lse = m + logf(ssum);
        if (lane < NCLS) out[(g0 + w) * NCLS + lane] = z - lse;
    }
}

// ---------------- launch ----------------
extern "C" void kernel_launch(void* const* d_in, const int* in_sizes, int n_in,
                              void* d_out, int out_size) {
    const float* x   = (const float*)d_in[0];
    const void*  ei  = d_in[1];
    const void*  bt  = d_in[2];
    const float* W   = (const float*)d_in[3];
    const float* b   = (const float*)d_in[4];
    const float* u   = (const float*)d_in[5];
    const float* g1  = (const float*)d_in[6];
    const float* be1 = (const float*)d_in[7];
    const float* g2  = (const float*)d_in[8];
    const float* be2 = (const float*)d_in[9];
    const float* w1  = (const float*)d_in[10];
    const float* b1  = (const float*)d_in[11];
    const float* w2  = (const float*)d_in[12];
    const float* b2  = (const float*)d_in[13];
    const float* w3  = (const float*)d_in[14];
    const float* b3  = (const float*)d_in[15];
    float* out = (float*)d_out;

    float *h1p = nullptr, *h2p = nullptr;
    cudaGetSymbolAddress((void**)&h1p, g_h1);
    cudaGetSymbolAddress((void**)&h2p, g_h2);

    k_fill<<<NBF + 5, 256>>>(ei, bt, W, u);
    k_spmm<1><<<NN / 8, 256>>>(x, h1p);
    k_spmm<0><<<NN / 8, 256>>>(h1p, h2p);
    k_matmul<<<dim3(3, NN / 128), 256>>>(x, W, b, bt);
    k_tail<<<GG / 2, L1O>>>(bt, g1, be1, g2, be2, w1, b1, w2, b2, w3, b3, out);
}

// round 12
// speedup vs baseline: 1.1910x; 1.1910x over previous
#include <cuda_runtime.h>
#include <math.h>

#define NN   8192
#define EE   262144
#define CIN  64
#define DD   192      // IN_C*K = OUT_C*K
#define GG   64
#define NCLS 10
#define D3   576      // 3*DD
#define L1O  384
#define L2O  192
#define MAXDEG 128
#define BNEPS 1e-5f
#define NBF  (EE / 256)   // 1024 fill blocks

// ---------------- scratch (no allocations allowed) ----------------
__device__ int   g_is64_edge, g_is64_batch;
__device__ int   g_cnt[NN];
__device__ float g_dinv[NN];
__device__ int   g_slot[NN * MAXDEG];
__device__ float g_h1[NN * CIN];
__device__ float g_h2[NN * CIN];
__device__ float g_hlin[NN * DD];
__device__ float g_csum[DD], g_csq[DD];
__device__ float g_hg[GG * D3];
__device__ float g_invsigma;

__device__ __forceinline__ int rd_idx(const void* p, int i, int is64) {
    if (is64) return (int)((const long long*)p)[i];
    return ((const int*)p)[i];
}

// ---------------- init: zero per-call state + dtype detect + sigma ---------
// Every piece of mutable cross-kernel state is (re)established HERE, at the
// head of each kernel_launch call — no reliance on end-of-previous-call
// resets, so partial/interrupted replays cannot poison the next one.
__global__ void k_init(const void* ei, const void* bt,
                       const float* __restrict__ W, const float* __restrict__ u) {
    int t = threadIdx.x;
    if (blockIdx.x == 32) {
        if (t == 0) {
            // edge_index values < 8192: if int64, odd 32-bit words are all 0.
            const int* wd = (const int*)ei;
            int a = 0;
            #pragma unroll
            for (int k = 0; k < 64; k++) a |= wd[2 * k + 1];
            g_is64_edge = (a == 0) ? 1 : 0;
            // batch sorted 0..63: tail words (graph 63) nonzero iff int32.
            const int* wb = (const int*)bt;
            int bb = 0;
            #pragma unroll
            for (int k = NN - 64; k < NN; k++)
                if (k & 1) bb |= wb[k];
            g_is64_batch = (bb == 0) ? 1 : 0;
        }
        // sigma = ||W^T u||^2 / (||W^T u|| + 1e-12);  invsigma = 1/sigma
        __shared__ float red[256];
        __shared__ float su[DD];
        if (t < DD) su[t] = u[t];
        __syncthreads();
        float w = 0.f;
        if (t < DD) {
            #pragma unroll 8
            for (int i = 0; i < DD; i++) w += W[i * DD + t] * su[i];
        }
        red[t] = (t < DD) ? w * w : 0.f;
        __syncthreads();
        for (int off = 128; off > 0; off >>= 1) {
            if (t < off) red[t] += red[t + off];
            __syncthreads();
        }
        if (t == 0) {
            float n2 = red[0];
            g_invsigma = (sqrtf(n2) + 1e-12f) / n2;
        }
        return;
    }
    int i = blockIdx.x * 256 + t;
    if (i < NN) g_cnt[i] = 0;
    if (i < DD) { g_csum[i] = 0.f; g_csq[i] = 0.f; }
}

// ---------------- one-pass count + slot fill ----------------
__global__ void k_fill(const void* ei) {
    int e = blockIdx.x * 256 + threadIdx.x;
    int is64 = g_is64_edge;
    int r = rd_idx(ei, e, is64);
    int c = rd_idx(ei, EE + e, is64);
    int pos = atomicAdd(&g_cnt[r], 1);
    if (pos < MAXDEG) g_slot[r * MAXDEG + pos] = c;
}

// ---- gather SpMM: out[r] = in[r] - dinv[r]*sum_c dinv[c]*in[c]
// PASS1 computes dinv from cnt on the fly (rsqrt per edge) and caches g_dinv;
// PASS2 reads the cache.
template <int PASS1>
__global__ void k_spmm(const float* __restrict__ in, float* __restrict__ out) {
    int node = blockIdx.x * 8 + (threadIdx.x >> 5);
    int lane = threadIdx.x & 31;
    const float2* in2 = (const float2*)in;
    int cr = g_cnt[node];
    int cnt = min(cr, MAXDEG);
    float dvr;
    if (PASS1) {
        dvr = (cr > 0) ? rsqrtf((float)cr) : 0.f;
        if (lane == 0) g_dinv[node] = dvr;
    } else {
        dvr = g_dinv[node];
    }
    float2 sum = make_float2(0.f, 0.f);
    const int* sl = g_slot + node * MAXDEG;
    const int4* sl4 = (const int4*)sl;
    int j = 0;
    for (; j + 8 <= cnt; j += 8) {
        int4 a = sl4[j >> 2], b2 = sl4[(j >> 2) + 1];
        int c[8] = {a.x, a.y, a.z, a.w, b2.x, b2.y, b2.z, b2.w};
        float dv[8];
        #pragma unroll
        for (int k = 0; k < 8; k++) {
            if (PASS1) {
                int cc = g_cnt[c[k]];
                dv[k] = (cc > 0) ? rsqrtf((float)cc) : 0.f;
            } else {
                dv[k] = g_dinv[c[k]];
            }
        }
        #pragma unroll
        for (int k = 0; k < 8; k++) {
            float2 v = in2[c[k] * 32 + lane];
            sum.x += dv[k] * v.x;
            sum.y += dv[k] * v.y;
        }
    }
    for (; j < cnt; j++) {
        int c = sl[j];
        float dv;
        if (PASS1) {
            int cc = g_cnt[c];
            dv = (cc > 0) ? rsqrtf((float)cc) : 0.f;
        } else {
            dv = g_dinv[c];
        }
        float2 v = in2[c * 32 + lane];
        sum.x += dv * v.x;
        sum.y += dv * v.y;
    }
    float2 xv = in2[node * 32 + lane];
    ((float2*)out)[node * 32 + lane] =
        make_float2(xv.x - dvr * sum.x, xv.y - dvr * sum.y);
}

// ---------------- masked spectral linear + fused BN1 partial stats --------
// 128 rows x 64 cols per block, 256 threads, 8x4 micro-tile, BK=16.
// Block-lower-triangular mask => out-col tile obi needs only K < 64*(obi+1).
__global__ void k_matmul(const float* __restrict__ x, const float* __restrict__ W,
                         const float* __restrict__ b) {
    __shared__ float As[16][132];
    __shared__ float Bs[16][68];
    int obi = 2 - blockIdx.x;     // longest K first
    int ob = obi * 64;
    int kmax = 64 * (obi + 1);
    int rb = blockIdx.y * 128;
    int t = threadIdx.x;
    int tx = t & 15, ty = t >> 4;
    float acc[8][4];
    #pragma unroll
    for (int i = 0; i < 8; i++)
        #pragma unroll
        for (int j = 0; j < 4; j++) acc[i][j] = 0.f;
    float invs = g_invsigma;

    int lidx = t * 4;
    int lm = lidx >> 4;       // 0..63
    int lk = lidx & 15;       // 0,4,8,12

    for (int kb = 0; kb < kmax; kb += 16) {
        int kg = kb + lk;
        int seg = kg >> 6;
        const float* src = (seg == 0) ? x : ((seg == 1) ? g_h1 : g_h2);
        #pragma unroll
        for (int rep = 0; rep < 2; rep++) {
            int row = rb + lm + rep * 64;
            float4 v = *(const float4*)(src + row * CIN + (kg & 63));
            As[lk][lm + rep * 64]     = v.x;
            As[lk + 1][lm + rep * 64] = v.y;
            As[lk + 2][lm + rep * 64] = v.z;
            As[lk + 3][lm + rep * 64] = v.w;
        }
        {
            float4 v = *(const float4*)(W + (ob + lm) * DD + kg);
            Bs[lk][lm]     = v.x * invs;
            Bs[lk + 1][lm] = v.y * invs;
            Bs[lk + 2][lm] = v.z * invs;
            Bs[lk + 3][lm] = v.w * invs;
        }
        __syncthreads();
        #pragma unroll
        for (int kk = 0; kk < 16; kk++) {
            float av[8], bv[4];
            #pragma unroll
            for (int i = 0; i < 8; i++) av[i] = As[kk][ty * 8 + i];
            #pragma unroll
            for (int j = 0; j < 4; j++) bv[j] = Bs[kk][tx * 4 + j];
            #pragma unroll
            for (int i = 0; i < 8; i++)
                #pragma unroll
                for (int j = 0; j < 4; j++) acc[i][j] += av[i] * bv[j];
        }
        __syncthreads();
    }
    float bj[4];
    #pragma unroll
    for (int j = 0; j < 4; j++) bj[j] = b[ob + tx * 4 + j];
    #pragma unroll
    for (int i = 0; i < 8; i++) {
        int r = rb + ty * 8 + i;
        #pragma unroll
        for (int j = 0; j < 4; j++)
            g_hlin[r * DD + ob + tx * 4 + j] = acc[i][j] + bj[j];
    }
    // per-column partial BN stats over this tile's 128 rows
    float sj[4], qj[4];
    #pragma unroll
    for (int j = 0; j < 4; j++) {
        float s = 0.f, q = 0.f;
        #pragma unroll
        for (int i = 0; i < 8; i++) {
            float v = acc[i][j] + bj[j];
            s += v; q += v * v;
        }
        sj[j] = s; qj[j] = q;
    }
    __syncthreads();
    #pragma unroll
    for (int j = 0; j < 4; j++) {
        As[ty][tx * 4 + j] = sj[j];
        Bs[ty][tx * 4 + j] = qj[j];
    }
    __syncthreads();
    if (t < 64) {
        float s = 0.f, q = 0.f;
        #pragma unroll
        for (int k = 0; k < 16; k++) { s += As[k][t]; q += Bs[k][t]; }
        atomicAdd(&g_csum[ob + t], s);
        atomicAdd(&g_csq[ob + t], q);
    }
}

// ---------------- fused BN1-finalize + segment search + triple pooling ----
// 384 threads: two row-strided halves per graph, combined in smem.
__global__ void k_pool(const void* bt, const float* __restrict__ gamma,
                       const float* __restrict__ beta) {
    __shared__ int seg[2];
    __shared__ float ssum[DD], smax[DD];
    int g = blockIdx.x, t = threadIdx.x;
    int half = t / DD;        // 0 or 1
    int c = t - half * DD;
    if (t < 2) {
        int target = g + t;
        int is64 = g_is64_batch;
        int lo = 0, hi = NN;
        while (lo < hi) {
            int mid = (lo + hi) >> 1;
            if (rd_idx(bt, mid, is64) < target) lo = mid + 1; else hi = mid;
        }
        seg[t] = lo;
    }
    __syncthreads();
    int s = seg[0], e = seg[1];
    float mu = g_csum[c] * (1.f / NN);
    float var = g_csq[c] * (1.f / NN) - mu * mu;
    float rs = rsqrtf(var + BNEPS) * gamma[c];
    float be = beta[c];
    float sum = 0.f, mx = -INFINITY;
    for (int i = s + half; i < e; i += 2) {
        float h = (g_hlin[i * DD + c] - mu) * rs + be;
        sum += h;
        mx = fmaxf(mx, h);
    }
    if (half == 1) { ssum[c] = sum; smax[c] = mx; }
    __syncthreads();
    if (half == 0) {
        sum += ssum[c];
        mx = fmaxf(mx, smax[c]);
        int cnt = e - s;
        g_hg[g * D3 + c]          = sum / fmaxf((float)cnt, 1.f);
        g_hg[g * D3 + DD + c]     = sum;
        g_hg[g * D3 + 2 * DD + c] = (cnt > 0) ? mx : -INFINITY;
    }
}

// ---------------- fused BN2 + funnel MLP + log_softmax (2 graphs / block) --
__global__ void k_tail(const float* __restrict__ g2g, const float* __restrict__ g2b,
                       const float* __restrict__ w1, const float* __restrict__ b1,
                       const float* __restrict__ w2, const float* __restrict__ b2,
                       const float* __restrict__ w3, const float* __restrict__ b3,
                       float* __restrict__ out) {
    __shared__ float smu[D3], srs[D3];
    __shared__ float xr[2][D3];
    __shared__ float x1[2][L1O];
    __shared__ float x2[2][L2O];
    int t = threadIdx.x;              // 384
    int g0 = blockIdx.x * 2;
    int w = t >> 5, lane = t & 31;
    #pragma unroll
    for (int rep = 0; rep < 2; rep++) {
        int c = rep * 384 + w * 32 + lane;
        if (c < D3) {
            float s = 0.f, q = 0.f;
            #pragma unroll 4
            for (int gg = 0; gg < GG; gg++) {
                float v = g_hg[gg * D3 + c];
                s += v; q += v * v;
            }
            float m = s * (1.f / GG);
            float var = q * (1.f / GG) - m * m;
            smu[c] = m;
            srs[c] = rsqrtf(var + BNEPS);
        }
    }
    __syncthreads();
    for (int c = t; c < D3; c += L1O) {
        float ga = g2g[c], be = g2b[c], m = smu[c], r = srs[c];
        xr[0][c] = ga * (g_hg[g0 * D3 + c] - m) * r + be;
        xr[1][c] = ga * (g_hg[(g0 + 1) * D3 + c] - m) * r + be;
    }
    __syncthreads();
    {
        float a0 = b1[t], a1 = a0;
        const float4* wr = (const float4*)(w1 + t * D3);
        #pragma unroll 4
        for (int k = 0; k < D3 / 4; k++) {
            float4 wv = wr[k];
            a0 += xr[0][4 * k] * wv.x + xr[0][4 * k + 1] * wv.y
                + xr[0][4 * k + 2] * wv.z + xr[0][4 * k + 3] * wv.w;
            a1 += xr[1][4 * k] * wv.x + xr[1][4 * k + 1] * wv.y
                + xr[1][4 * k + 2] * wv.z + xr[1][4 * k + 3] * wv.w;
        }
        x1[0][t] = fmaxf(a0, 0.f);
        x1[1][t] = fmaxf(a1, 0.f);
    }
    __syncthreads();
    if (t < L2O) {
        float a0 = b2[t], a1 = a0;
        const float4* wr = (const float4*)(w2 + t * L1O);
        #pragma unroll 4
        for (int k = 0; k < L1O / 4; k++) {
            float4 wv = wr[k];
            a0 += x1[0][4 * k] * wv.x + x1[0][4 * k + 1] * wv.y
                + x1[0][4 * k + 2] * wv.z + x1[0][4 * k + 3] * wv.w;
            a1 += x1[1][4 * k] * wv.x + x1[1][4 * k + 1] * wv.y
                + x1[1][4 * k + 2] * wv.z + x1[1][4 * k + 3] * wv.w;
        }
        x2[0][t] = fmaxf(a0, 0.f);
        x2[1][t] = fmaxf(a1, 0.f);
    }
    __syncthreads();
    if (w < 2) {
        float z = -INFINITY;
        if (lane < NCLS) {
            z = b3[lane];
            const float4* wr = (const float4*)(w3 + lane * L2O);
            #pragma unroll 4
            for (int k = 0; k < L2O / 4; k++) {
                float4 wv = wr[k];
                z += x2[w][4 * k] * wv.x + x2[w][4 * k + 1] * wv.y
                   + x2[w][4 * k + 2] * wv.z + x2[w][4 * k + 3] * wv.w;
            }
        }
        float m = z;
        #pragma unroll
        for (int off = 16; off > 0; off >>= 1)
            m = fmaxf(m, __shfl_xor_sync(0xffffffff, m, off));
        float ex = (lane < NCLS) ? __expf(z - m) : 0.f;
        float ssum = ex;
        #pragma unroll
        for (int off = 16; off > 0; off >>= 1)
            ssum += __shfl_xor_sync(0xffffffff, ssum, off);
        float lse = m + logf(ssum);
        if (lane < NCLS) out[(g0 + w) * NCLS + lane] = z - lse;
    }
}

// ---------------- launch ----------------
extern "C" void kernel_launch(void* const* d_in, const int* in_sizes, int n_in,
                              void* d_out, int out_size) {
    const float* x   = (const float*)d_in[0];
    const void*  ei  = d_in[1];
    const void*  bt  = d_in[2];
    const float* W   = (const float*)d_in[3];
    const float* b   = (const float*)d_in[4];
    const float* u   = (const float*)d_in[5];
    const float* g1  = (const float*)d_in[6];
    const float* be1 = (const float*)d_in[7];
    const float* g2  = (const float*)d_in[8];
    const float* be2 = (const float*)d_in[9];
    const float* w1  = (const float*)d_in[10];
    const float* b1  = (const float*)d_in[11];
    const float* w2  = (const float*)d_in[12];
    const float* b2  = (const float*)d_in[13];
    const float* w3  = (const float*)d_in[14];
    const float* b3  = (const float*)d_in[15];
    float* out = (float*)d_out;

    float *h1p = nullptr, *h2p = nullptr;
    cudaGetSymbolAddress((void**)&h1p, g_h1);
    cudaGetSymbolAddress((void**)&h2p, g_h2);

    k_init<<<33, 256>>>(ei, bt, W, u);
    k_fill<<<NBF, 256>>>(ei);
    k_spmm<1><<<NN / 8, 256>>>(x, h1p);
    k_spmm<0><<<NN / 8, 256>>>(h1p, h2p);
    k_matmul<<<dim3(3, NN / 128), 256>>>(x, W, b);
    k_pool<<<GG, 2 * DD>>>(bt, g1, be1);
    k_tail<<<GG / 2, L1O>>>(g2, be2, w1, b1, w2, b2, w3, b3, out);
}